// round 1
// baseline (speedup 1.0000x reference)
#include <cuda_runtime.h>

// ---------------------------------------------------------------------------
// QuantizedEmbedding (VQ-VAE codebook + EMA update), GB300 sm_103a
// Inputs (metadata order): ze [32,1024,256] f32, embedW [8192,256] f32,
//                          mt [8192,256] f32, Nt [8192] f32
// Output (concatenated f32): zq_st[N*D], commit[1], zq_idx[N] (as float),
//                            embedW_new[K*D], mt_new[K*D], Nt_new[K]
// ---------------------------------------------------------------------------

#define KC   8192      // num codes
#define DD   256       // embed dim
#define NP   32768     // num points (B*T)
#define GMA  0.99f
#define OMG  0.01f     // 1 - gamma
#define EPSV 1e-5f

// output offsets
#define OFF_ZQ     0LL
#define OFF_COMMIT 8388608LL                 // N*D
#define OFF_IDX    8388609LL
#define OFF_EW     8421377LL                 // OFF_IDX + N
#define OFF_MT     10518529LL                // OFF_EW + K*D
#define OFF_NT     12615681LL                // OFF_MT + K*D

// ---- device scratch (no dynamic allocation allowed) ----
__device__ float g_wsq[KC];
__device__ int   g_idx[NP];
__device__ float g_nt[KC];
__device__ float g_st[KC * DD];
__device__ float g_commit;
__device__ float g_nsum;
__device__ float g_NtNew[KC];

// ---------------------------------------------------------------------------
// Zero scratch (graph-replay safe: every launch starts clean)
// ---------------------------------------------------------------------------
__global__ void zero_kernel() {
    long long i = (long long)blockIdx.x * blockDim.x + threadIdx.x;
    long long stride = (long long)gridDim.x * blockDim.x;
    for (long long j = i; j < (long long)KC * DD; j += stride) g_st[j] = 0.0f;
    for (long long j = i; j < KC; j += stride) g_nt[j] = 0.0f;
    if (i == 0) { g_commit = 0.0f; g_nsum = 0.0f; }
}

// ---------------------------------------------------------------------------
// ||w_k||^2 : one warp per code row
// ---------------------------------------------------------------------------
__global__ void wsq_kernel(const float* __restrict__ W) {
    int w = (blockIdx.x * blockDim.x + threadIdx.x) >> 5;
    int lane = threadIdx.x & 31;
    if (w >= KC) return;
    const float4* row = reinterpret_cast<const float4*>(W + (long long)w * DD);
    float s = 0.0f;
    #pragma unroll
    for (int i = 0; i < 2; i++) {
        float4 v = row[lane + 32 * i];
        s += v.x * v.x + v.y * v.y + v.z * v.z + v.w * v.w;
    }
    #pragma unroll
    for (int o = 16; o; o >>= 1) s += __shfl_down_sync(0xFFFFFFFFu, s, o);
    if (lane == 0) g_wsq[w] = s;
}

// ---------------------------------------------------------------------------
// Argmin GEMM:  score[n,k] = ||w_k||^2 - 2 * <z_n, w_k>,  take argmin over k.
// 128x128 tile, 8-deep chunks, 8x8 micro-tile per thread, f32x2 packed FMA.
// Running best kept as 64-bit key (monotonic-float << 32 | idx): min over keys
// gives min score with lowest index on exact ties (matches jnp.argmin).
// ---------------------------------------------------------------------------
#define BN 128
#define BK 128
#define BD 8

__device__ __forceinline__ unsigned long long pack2(float x) {
    unsigned long long r;
    unsigned u = __float_as_uint(x);
    asm("mov.b64 %0, {%1, %1};" : "=l"(r) : "r"(u));
    return r;
}
__device__ __forceinline__ void fma2(unsigned long long& d,
                                     unsigned long long a,
                                     unsigned long long b) {
    asm("fma.rn.f32x2 %0, %1, %2, %0;" : "+l"(d) : "l"(a), "l"(b));
}
__device__ __forceinline__ unsigned fmono(float f) {
    unsigned u = __float_as_uint(f);
    return (u & 0x80000000u) ? ~u : (u | 0x80000000u);
}

__global__ void __launch_bounds__(256) argmin_kernel(const float* __restrict__ ze,
                                                     const float* __restrict__ W) {
    __shared__ float As[BD][BN];
    __shared__ float Bs[BD][BK];
    __shared__ float Ws[BK];
    __shared__ unsigned long long s_red[BN][17];   // padded to kill bank conflicts

    const int tid  = threadIdx.x;
    const int tx   = tid & 15;        // code direction (16 threads)
    const int ty   = tid >> 4;        // point direction (16 threads)
    const int row0 = ty * 8;
    const int col0 = tx * 8;
    const int n0   = blockIdx.x * BN;

    const int lrow  = tid >> 1;       // 0..127 (load row)
    const int lhalf = (tid & 1) * 4;  // 0 or 4 (which float4 of the 8-chunk)

    unsigned long long best[8];
    #pragma unroll
    for (int i = 0; i < 8; i++) best[i] = ~0ull;

    for (int k0 = 0; k0 < KC; k0 += BK) {
        unsigned long long acc2[8][4];
        #pragma unroll
        for (int i = 0; i < 8; i++)
            #pragma unroll
            for (int j = 0; j < 4; j++) acc2[i][j] = 0ull;

        for (int d0 = 0; d0 < DD; d0 += BD) {
            // issue global loads early (overlap with barrier drain)
            float4 av = *reinterpret_cast<const float4*>(
                ze + (long long)(n0 + lrow) * DD + d0 + lhalf);
            float4 bv = *reinterpret_cast<const float4*>(
                W + (long long)(k0 + lrow) * DD + d0 + lhalf);
            __syncthreads();   // previous chunk's readers done
            As[lhalf + 0][lrow] = av.x; As[lhalf + 1][lrow] = av.y;
            As[lhalf + 2][lrow] = av.z; As[lhalf + 3][lrow] = av.w;
            Bs[lhalf + 0][lrow] = bv.x; Bs[lhalf + 1][lrow] = bv.y;
            Bs[lhalf + 2][lrow] = bv.z; Bs[lhalf + 3][lrow] = bv.w;
            if (d0 == 0 && tid < BK) Ws[tid] = g_wsq[k0 + tid];
            __syncthreads();

            #pragma unroll
            for (int dk = 0; dk < BD; dk++) {
                float a[8];
                *reinterpret_cast<float4*>(a)     = *reinterpret_cast<const float4*>(&As[dk][row0]);
                *reinterpret_cast<float4*>(a + 4) = *reinterpret_cast<const float4*>(&As[dk][row0 + 4]);
                unsigned long long b2[4];
                *reinterpret_cast<float4*>(&b2[0]) = *reinterpret_cast<const float4*>(&Bs[dk][col0]);
                *reinterpret_cast<float4*>(&b2[2]) = *reinterpret_cast<const float4*>(&Bs[dk][col0 + 4]);
                #pragma unroll
                for (int i = 0; i < 8; i++) {
                    unsigned long long ap = pack2(a[i]);
                    fma2(acc2[i][0], ap, b2[0]);
                    fma2(acc2[i][1], ap, b2[1]);
                    fma2(acc2[i][2], ap, b2[2]);
                    fma2(acc2[i][3], ap, b2[3]);
                }
            }
        }

        // fold this k-tile into the running argmin
        #pragma unroll
        for (int i = 0; i < 8; i++) {
            #pragma unroll
            for (int jp = 0; jp < 4; jp++) {
                unsigned lo, hi;
                asm("mov.b64 {%0, %1}, %2;" : "=r"(lo), "=r"(hi) : "l"(acc2[i][jp]));
                int c0 = k0 + col0 + jp * 2;
                float s0 = fmaf(-2.0f, __uint_as_float(lo), Ws[col0 + jp * 2]);
                float s1 = fmaf(-2.0f, __uint_as_float(hi), Ws[col0 + jp * 2 + 1]);
                unsigned long long k0u = ((unsigned long long)fmono(s0) << 32) | (unsigned)c0;
                unsigned long long k1u = ((unsigned long long)fmono(s1) << 32) | (unsigned)(c0 + 1);
                if (k0u < best[i]) best[i] = k0u;
                if (k1u < best[i]) best[i] = k1u;
            }
        }
    }

    // cross-thread (tx) reduction per point
    #pragma unroll
    for (int i = 0; i < 8; i++) s_red[row0 + i][tx] = best[i];
    __syncthreads();
    if (tid < BN) {
        unsigned long long m = ~0ull;
        #pragma unroll
        for (int t = 0; t < 16; t++) {
            unsigned long long v = s_red[tid][t];
            if (v < m) m = v;
        }
        g_idx[n0 + tid] = (int)(m & 0xFFFFFFFFu);
    }
}

// ---------------------------------------------------------------------------
// Gather zq (zq_st == zq numerically), commit partials, scatter EMA sums.
// One block per point, 256 threads = 256 dims.
// ---------------------------------------------------------------------------
__global__ void gather_scatter_kernel(const float* __restrict__ ze,
                                      const float* __restrict__ W,
                                      float* __restrict__ out) {
    int n = blockIdx.x;
    int d = threadIdx.x;
    int c = g_idx[n];
    float w = W[(long long)c * DD + d];
    float z = ze[(long long)n * DD + d];
    out[OFF_ZQ + (long long)n * DD + d] = w;
    float diff = w - z;
    float sq = diff * diff;
    atomicAdd(&g_st[(long long)c * DD + d], z);

    // block reduce sq
    #pragma unroll
    for (int o = 16; o; o >>= 1) sq += __shfl_down_sync(0xFFFFFFFFu, sq, o);
    __shared__ float red[8];
    int wid = d >> 5, lane = d & 31;
    if (lane == 0) red[wid] = sq;
    __syncthreads();
    if (wid == 0) {
        float v = (lane < 8) ? red[lane] : 0.0f;
        #pragma unroll
        for (int o = 4; o; o >>= 1) v += __shfl_down_sync(0xFFFFFFFFu, v, o);
        if (lane == 0) atomicAdd(&g_commit, v);
    }
    if (d == 0) {
        atomicAdd(&g_nt[c], 1.0f);
        out[OFF_IDX + n] = (float)c;
    }
}

// ---------------------------------------------------------------------------
// Nt_new + total count n
// ---------------------------------------------------------------------------
__global__ void nt_kernel(const float* __restrict__ Nt, float* __restrict__ out) {
    int k = blockIdx.x * 256 + threadIdx.x;
    float v = GMA * Nt[k] + OMG * g_nt[k];
    g_NtNew[k] = v;
    out[OFF_NT + k] = v;
    float s = v;
    #pragma unroll
    for (int o = 16; o; o >>= 1) s += __shfl_down_sync(0xFFFFFFFFu, s, o);
    __shared__ float red[8];
    int wid = threadIdx.x >> 5, lane = threadIdx.x & 31;
    if (lane == 0) red[wid] = s;
    __syncthreads();
    if (wid == 0) {
        float v2 = (lane < 8) ? red[lane] : 0.0f;
        #pragma unroll
        for (int o = 4; o; o >>= 1) v2 += __shfl_down_sync(0xFFFFFFFFu, v2, o);
        if (lane == 0) atomicAdd(&g_nsum, v2);
    }
}

// ---------------------------------------------------------------------------
// mt_new, embedW_new, commit finalize
// ---------------------------------------------------------------------------
__global__ void final_kernel(const float* __restrict__ mt, float* __restrict__ out) {
    long long i = (long long)blockIdx.x * 256 + threadIdx.x;
    int k = (int)(i >> 8);                  // i / D
    float mtn = GMA * mt[i] + OMG * g_st[i];
    out[OFF_MT + i] = mtn;
    float n = g_nsum;
    float Nn = (g_NtNew[k] + EPSV) * n / (n + (float)KC * EPSV);
    out[OFF_EW + i] = mtn / Nn;
    if (i == 0) out[OFF_COMMIT] = g_commit / (float)((long long)NP * DD);
}

// ---------------------------------------------------------------------------
extern "C" void kernel_launch(void* const* d_in, const int* in_sizes, int n_in,
                              void* d_out, int out_size) {
    const float* ze = (const float*)d_in[0];
    const float* W  = (const float*)d_in[1];
    const float* mt = (const float*)d_in[2];
    const float* Nt = (const float*)d_in[3];
    float* out = (float*)d_out;
    (void)in_sizes; (void)n_in; (void)out_size;

    zero_kernel<<<2048, 256>>>();
    wsq_kernel<<<(KC * 32) / 256, 256>>>(W);
    argmin_kernel<<<NP / BN, 256>>>(ze, W);
    gather_scatter_kernel<<<NP, 256>>>(ze, W, out);
    nt_kernel<<<KC / 256, 256>>>(Nt, out);
    final_kernel<<<(KC * DD) / 256, 256>>>(mt, out);
}

// round 4
// speedup vs baseline: 5.0876x; 5.0876x over previous
#include <cuda_runtime.h>
#include <cuda_fp16.h>
#include <cstdint>

// ---------------------------------------------------------------------------
// QuantizedEmbedding (VQ-VAE codebook + EMA update), GB300 sm_103a
// Round 4: fp16 HMMA (mma.sync) argmin GEMM, top-4 candidates, fp32 rescore.
// (tcgen05 unusable: harness PTX target is compute_103, not compute_103a.)
// ---------------------------------------------------------------------------

#define KC   8192
#define DD   256
#define NP   32768
#define GMA  0.99f
#define OMG  0.01f
#define EPSV 1e-5f

#define OFF_ZQ     0LL
#define OFF_COMMIT 8388608LL
#define OFF_IDX    8388609LL
#define OFF_EW     8421377LL
#define OFF_MT     10518529LL
#define OFF_NT     12615681LL

// ---- device scratch ----
__device__ __align__(256) __half g_Ah[(size_t)NP * DD];   // 16.8 MB fp16 points
__device__ __align__(256) __half g_Bh[(size_t)KC * DD];   //  4.2 MB fp16 codes
__device__ float g_wsq[KC];
__device__ int4  g_cand[NP];
__device__ float g_nt[KC];
__device__ float g_st[KC * DD];
__device__ float g_commit;
__device__ float g_nsum;
__device__ float g_NtNew[KC];

// ===========================================================================
// helpers
// ===========================================================================
__device__ __forceinline__ uint32_t smem_u32(const void* p) {
    uint32_t a;
    asm("{ .reg .u64 t; cvta.to.shared.u64 t, %1; cvt.u32.u64 %0, t; }"
        : "=r"(a) : "l"(p));
    return a;
}
__device__ __forceinline__ void cp16(uint32_t dst, const void* src) {
    asm volatile("cp.async.cg.shared.global [%0], [%1], 16;"
                 :: "r"(dst), "l"(src) : "memory");
}
__device__ __forceinline__ void cp_commit() {
    asm volatile("cp.async.commit_group;" ::: "memory");
}
__device__ __forceinline__ void cp_wait2() {
    asm volatile("cp.async.wait_group 2;" ::: "memory");
}
__device__ __forceinline__ void ldsm4(uint32_t* r, uint32_t addr) {
    asm volatile("ldmatrix.sync.aligned.m8n8.x4.shared.b16 {%0,%1,%2,%3}, [%4];"
                 : "=r"(r[0]), "=r"(r[1]), "=r"(r[2]), "=r"(r[3]) : "r"(addr));
}
__device__ __forceinline__ void mma16816(float* c, const uint32_t* a,
                                         uint32_t b0, uint32_t b1) {
    asm volatile(
        "mma.sync.aligned.m16n8k16.row.col.f32.f16.f16.f32 "
        "{%0,%1,%2,%3}, {%4,%5,%6,%7}, {%8,%9}, {%0,%1,%2,%3};"
        : "+f"(c[0]), "+f"(c[1]), "+f"(c[2]), "+f"(c[3])
        : "r"(a[0]), "r"(a[1]), "r"(a[2]), "r"(a[3]), "r"(b0), "r"(b1));
}
__device__ __forceinline__ unsigned fmono(float f) {
    unsigned u = __float_as_uint(f);
    return (u & 0x80000000u) ? ~u : (u | 0x80000000u);
}
__device__ __forceinline__ void ins4(unsigned long long* a, unsigned long long v) {
    if (v < a[3]) {
        if (v < a[2]) {
            a[3] = a[2];
            if (v < a[1]) {
                a[2] = a[1];
                if (v < a[0]) { a[1] = a[0]; a[0] = v; } else a[1] = v;
            } else a[2] = v;
        } else a[3] = v;
    }
}

// ===========================================================================
// small kernels
// ===========================================================================
__global__ void zero_kernel() {
    long long i = (long long)blockIdx.x * blockDim.x + threadIdx.x;
    long long stride = (long long)gridDim.x * blockDim.x;
    for (long long j = i; j < (long long)KC * DD; j += stride) g_st[j] = 0.0f;
    for (long long j = i; j < KC; j += stride) g_nt[j] = 0.0f;
    if (i == 0) { g_commit = 0.0f; g_nsum = 0.0f; }
}

__global__ void wsq_kernel(const float* __restrict__ W) {
    int w = (blockIdx.x * blockDim.x + threadIdx.x) >> 5;
    int lane = threadIdx.x & 31;
    if (w >= KC) return;
    const float4* row = reinterpret_cast<const float4*>(W + (size_t)w * DD);
    float s = 0.0f;
    #pragma unroll
    for (int i = 0; i < 2; i++) {
        float4 v = row[lane + 32 * i];
        s += v.x * v.x + v.y * v.y + v.z * v.z + v.w * v.w;
    }
    #pragma unroll
    for (int o = 16; o; o >>= 1) s += __shfl_down_sync(0xFFFFFFFFu, s, o);
    if (lane == 0) g_wsq[w] = s;
}

__global__ void conv_ze_kernel(const float* __restrict__ src) {
    size_t i = ((size_t)blockIdx.x * 256 + threadIdx.x) * 8;
    float4 v0 = *reinterpret_cast<const float4*>(src + i);
    float4 v1 = *reinterpret_cast<const float4*>(src + i + 4);
    union { uint4 u; __half2 h[4]; } pk;
    pk.h[0] = __floats2half2_rn(v0.x, v0.y);
    pk.h[1] = __floats2half2_rn(v0.z, v0.w);
    pk.h[2] = __floats2half2_rn(v1.x, v1.y);
    pk.h[3] = __floats2half2_rn(v1.z, v1.w);
    *reinterpret_cast<uint4*>(g_Ah + i) = pk.u;
}
__global__ void conv_w_kernel(const float* __restrict__ src) {
    size_t i = ((size_t)blockIdx.x * 256 + threadIdx.x) * 8;
    float4 v0 = *reinterpret_cast<const float4*>(src + i);
    float4 v1 = *reinterpret_cast<const float4*>(src + i + 4);
    union { uint4 u; __half2 h[4]; } pk;
    pk.h[0] = __floats2half2_rn(v0.x, v0.y);
    pk.h[1] = __floats2half2_rn(v0.z, v0.w);
    pk.h[2] = __floats2half2_rn(v1.x, v1.y);
    pk.h[3] = __floats2half2_rn(v1.z, v1.w);
    *reinterpret_cast<uint4*>(g_Bh + i) = pk.u;
}

// ===========================================================================
// HMMA argmin GEMM.
//   CTA: 128 points x 8192 codes. A resident in SMEM (4 k64-chunks, 64 KB).
//   B streamed: 32 N-tiles of 256 codes x (4 k64-chunks), 4-buffer cp.async
//   ring. 8 warps = 2(M) x 4(N); warp tile 64x64; m16n8k16 fp16->fp32.
//   Epilogue: score = wsq - 2*dot, running top-2 per (thread,row); final
//   hierarchical merge -> global top-4 candidates per point.
// ===========================================================================
#define NTILES 32
#define GTOT   128              // 32 n-tiles * 4 k-chunks
#define SM_A_BYTES 65536
#define SM_B_BYTES 131072       // 4 x 32 KB
#define SMEM_BYTES (SM_A_BYTES + SM_B_BYTES)

__device__ __forceinline__ void load_B_chunk(uint32_t dstBase, int nt, int kc,
                                             int tid) {
    const __half* src0 = g_Bh + (size_t)nt * 256 * DD + kc * 64;
    #pragma unroll
    for (int i = 0; i < 8; i++) {
        int v = tid + 256 * i;          // 0..2047
        int row = v >> 3, c = v & 7;    // row: code in tile, c: 16B chunk
        const void* src = src0 + (size_t)row * DD + c * 8;
        uint32_t dst = dstBase + row * 128 + (((c ^ (row & 7))) << 4);
        cp16(dst, src);
    }
}

__global__ void __launch_bounds__(256, 1) argmin_gemm_kernel() {
    extern __shared__ char smem[];
    const uint32_t sb = smem_u32(smem);
    const uint32_t Ab = sb;
    const uint32_t Bb = sb + SM_A_BYTES;

    const int tid  = threadIdx.x;
    const int lane = tid & 31;
    const int wid  = tid >> 5;
    const int R0   = (wid >> 2) * 64;     // warp M offset (0/64)
    const int C0   = (wid & 3) * 64;      // warp N offset within tile
    const int n0   = blockIdx.x * 128;

    // ---- prologue: A (resident) + B chunks g=0,1 ----
    #pragma unroll
    for (int i = 0; i < 16; i++) {
        int v = tid + 256 * i;            // 0..4095
        int row = v >> 5, gc = v & 31;
        int kc = gc >> 3, c = gc & 7;
        const void* src = g_Ah + (size_t)(n0 + row) * DD + gc * 8;
        uint32_t dst = Ab + kc * 16384 + row * 128 + (((c ^ (row & 7))) << 4);
        cp16(dst, src);
    }
    load_B_chunk(Bb + 0 * 32768, 0, 0, tid);
    cp_commit();
    load_B_chunk(Bb + 1 * 32768, 0, 1, tid);
    cp_commit();

    // per-lane ldmatrix row components
    const int rl = (lane & 7) | (((lane >> 3) & 1) << 3);  // 0..15
    const int kh = (lane >> 4) & 1;                        // k half (0/1)

    float acc[4][8][4];
    #pragma unroll
    for (int t = 0; t < 4; t++)
        #pragma unroll
        for (int j = 0; j < 8; j++)
            #pragma unroll
            for (int e = 0; e < 4; e++) acc[t][j][e] = 0.0f;

    const float FINF = __int_as_float(0x7f800000);
    float s1[8], s2[8]; int i1[8], i2[8];
    #pragma unroll
    for (int r = 0; r < 8; r++) { s1[r] = FINF; s2[r] = FINF; i1[r] = 0; i2[r] = 0; }

    for (int g = 0; g < GTOT; ++g) {
        const int kc = g & 3, nt = g >> 2;
        // prefetch chunk g+2 into buffer (g+2)&3
        if (g + 2 < GTOT)
            load_B_chunk(Bb + ((g + 2) & 3) * 32768, (g + 2) >> 2, (g + 2) & 3, tid);
        cp_commit();
        cp_wait2();
        __syncthreads();

        const uint32_t Bbuf = Bb + (g & 3) * 32768;
        const uint32_t Achk = Ab + kc * 16384;

        #pragma unroll
        for (int s = 0; s < 4; s++) {
            const int c16 = s * 2 + kh;
            uint32_t a[4][4];
            #pragma unroll
            for (int t = 0; t < 4; t++) {
                int row = R0 + t * 16 + rl;
                uint32_t addr = Achk + row * 128 + (((c16 ^ (row & 7))) << 4);
                ldsm4(a[t], addr);
            }
            uint32_t bf[8][2];
            #pragma unroll
            for (int p = 0; p < 4; p++) {
                int row = C0 + p * 16 + rl;
                uint32_t addr = Bbuf + row * 128 + (((c16 ^ (row & 7))) << 4);
                uint32_t r4[4];
                ldsm4(r4, addr);
                bf[2 * p][0] = r4[0]; bf[2 * p][1] = r4[2];
                bf[2 * p + 1][0] = r4[1]; bf[2 * p + 1][1] = r4[3];
            }
            #pragma unroll
            for (int t = 0; t < 4; t++)
                #pragma unroll
                for (int j = 0; j < 8; j++)
                    mma16816(acc[t][j], a[t], bf[j][0], bf[j][1]);
        }

        if (kc == 3) {
            // fold tile nt into running top-2 per (thread,row); reset acc
            const int cb0 = nt * 256 + C0 + (lane & 3) * 2;
            #pragma unroll
            for (int j = 0; j < 8; j++) {
                float2 wq = *reinterpret_cast<const float2*>(&g_wsq[cb0 + j * 8]);
                #pragma unroll
                for (int t = 0; t < 4; t++) {
                    #pragma unroll
                    for (int e = 0; e < 4; e++) {
                        const int lr = t * 2 + (e >> 1);
                        const float wv = (e & 1) ? wq.y : wq.x;
                        const float sc = fmaf(-2.0f, acc[t][j][e], wv);
                        const int col = cb0 + j * 8 + (e & 1);
                        if (sc < s1[lr]) {
                            s2[lr] = s1[lr]; i2[lr] = i1[lr];
                            s1[lr] = sc;     i1[lr] = col;
                        } else if (sc < s2[lr]) {
                            s2[lr] = sc; i2[lr] = col;
                        }
                        acc[t][j][e] = 0.0f;
                    }
                }
            }
        }
    }

    // ---- final reduction: quad merge -> smem -> per-row top-4 ----
    unsigned long long* red = reinterpret_cast<unsigned long long*>(smem + SM_A_BYTES);
    const int ni = wid & 3;
    __syncthreads();   // everyone past last compute before aliasing B as red

    #pragma unroll
    for (int r = 0; r < 8; r++) {
        const int t = r >> 1, h = r & 1;
        const int row = R0 + t * 16 + (lane >> 2) + h * 8;
        unsigned long long arr[4];
        arr[0] = ((unsigned long long)fmono(s1[r]) << 32) | (unsigned)i1[r];
        arr[1] = ((unsigned long long)fmono(s2[r]) << 32) | (unsigned)i2[r];
        arr[2] = ~0ull; arr[3] = ~0ull;
        #pragma unroll
        for (int off = 1; off <= 2; off <<= 1) {
            unsigned long long o0 = __shfl_xor_sync(0xFFFFFFFFu, arr[0], off);
            unsigned long long o1 = __shfl_xor_sync(0xFFFFFFFFu, arr[1], off);
            unsigned long long o2 = __shfl_xor_sync(0xFFFFFFFFu, arr[2], off);
            unsigned long long o3 = __shfl_xor_sync(0xFFFFFFFFu, arr[3], off);
            ins4(arr, o0); ins4(arr, o1); ins4(arr, o2); ins4(arr, o3);
        }
        if ((lane & 3) == 0) {
            #pragma unroll
            for (int k = 0; k < 4; k++) red[(row * 4 + ni) * 4 + k] = arr[k];
        }
    }
    __syncthreads();

    if (tid < 128) {
        unsigned long long a[4] = {~0ull, ~0ull, ~0ull, ~0ull};
        #pragma unroll
        for (int w = 0; w < 4; w++)
            #pragma unroll
            for (int k = 0; k < 4; k++) ins4(a, red[(tid * 4 + w) * 4 + k]);
        g_cand[n0 + tid] = make_int4((int)(a[0] & 0xFFFFFFFFu),
                                     (int)(a[1] & 0xFFFFFFFFu),
                                     (int)(a[2] & 0xFFFFFFFFu),
                                     (int)(a[3] & 0xFFFFFFFFu));
    }
}

// ===========================================================================
// Exact fp32 rescore of top-4 + gather zq + EMA scatter + commit partials
// ===========================================================================
__global__ void rescore_gather_kernel(const float* __restrict__ ze,
                                      const float* __restrict__ W,
                                      float* __restrict__ out) {
    const int n = blockIdx.x;
    const int d = threadIdx.x;
    const int4 c = g_cand[n];
    const float z = ze[(size_t)n * DD + d];
    float w[4], p[4];
    w[0] = W[(size_t)c.x * DD + d];
    w[1] = W[(size_t)c.y * DD + d];
    w[2] = W[(size_t)c.z * DD + d];
    w[3] = W[(size_t)c.w * DD + d];
    #pragma unroll
    for (int j = 0; j < 4; j++) p[j] = z * w[j];
    #pragma unroll
    for (int o = 16; o; o >>= 1)
        #pragma unroll
        for (int j = 0; j < 4; j++)
            p[j] += __shfl_down_sync(0xFFFFFFFFu, p[j], o);
    __shared__ float rp[8][4];
    __shared__ int spick;
    const int lw = d >> 5, ln = d & 31;
    if (ln == 0) {
        #pragma unroll
        for (int j = 0; j < 4; j++) rp[lw][j] = p[j];
    }
    __syncthreads();
    if (d == 0) {
        int ci[4] = {c.x, c.y, c.z, c.w};
        float bs = __int_as_float(0x7f800000);   // +inf
        int bi = 0x7FFFFFFF, bj = 0;
        #pragma unroll
        for (int j = 0; j < 4; j++) {
            float dot = 0.0f;
            #pragma unroll
            for (int i = 0; i < 8; i++) dot += rp[i][j];
            float s = fmaf(-2.0f, dot, g_wsq[ci[j]]);
            if (s < bs || (s == bs && ci[j] < bi)) { bs = s; bi = ci[j]; bj = j; }
        }
        spick = bj;
    }
    __syncthreads();
    const int pick = spick;
    const int cb = (pick == 0) ? c.x : (pick == 1) ? c.y : (pick == 2) ? c.z : c.w;
    const float wv = (pick == 0) ? w[0] : (pick == 1) ? w[1]
                   : (pick == 2) ? w[2] : w[3];
    out[OFF_ZQ + (size_t)n * DD + d] = wv;
    const float diff = wv - z;
    float sq = diff * diff;
    atomicAdd(&g_st[(size_t)cb * DD + d], z);
    #pragma unroll
    for (int o = 16; o; o >>= 1) sq += __shfl_down_sync(0xFFFFFFFFu, sq, o);
    __shared__ float red[8];
    if (ln == 0) red[lw] = sq;
    __syncthreads();
    if (lw == 0) {
        float v = (ln < 8) ? red[ln] : 0.0f;
        #pragma unroll
        for (int o = 4; o; o >>= 1) v += __shfl_down_sync(0xFFFFFFFFu, v, o);
        if (ln == 0) atomicAdd(&g_commit, v);
    }
    if (d == 0) {
        atomicAdd(&g_nt[cb], 1.0f);
        out[OFF_IDX + n] = (float)cb;
    }
}

// ===========================================================================
// Nt / final
// ===========================================================================
__global__ void nt_kernel(const float* __restrict__ Nt, float* __restrict__ out) {
    int k = blockIdx.x * 256 + threadIdx.x;
    float v = GMA * Nt[k] + OMG * g_nt[k];
    g_NtNew[k] = v;
    out[OFF_NT + k] = v;
    float s = v;
    #pragma unroll
    for (int o = 16; o; o >>= 1) s += __shfl_down_sync(0xFFFFFFFFu, s, o);
    __shared__ float red[8];
    int wid = threadIdx.x >> 5, lane = threadIdx.x & 31;
    if (lane == 0) red[wid] = s;
    __syncthreads();
    if (wid == 0) {
        float v2 = (lane < 8) ? red[lane] : 0.0f;
        #pragma unroll
        for (int o = 4; o; o >>= 1) v2 += __shfl_down_sync(0xFFFFFFFFu, v2, o);
        if (lane == 0) atomicAdd(&g_nsum, v2);
    }
}

__global__ void final_kernel(const float* __restrict__ mt, float* __restrict__ out) {
    long long i = (long long)blockIdx.x * 256 + threadIdx.x;
    int k = (int)(i >> 8);
    float mtn = GMA * mt[i] + OMG * g_st[i];
    out[OFF_MT + i] = mtn;
    float n = g_nsum;
    float Nn = (g_NtNew[k] + EPSV) * n / (n + (float)KC * EPSV);
    out[OFF_EW + i] = mtn / Nn;
    if (i == 0) out[OFF_COMMIT] = g_commit / (float)((long long)NP * DD);
}

// ===========================================================================
extern "C" void kernel_launch(void* const* d_in, const int* in_sizes, int n_in,
                              void* d_out, int out_size) {
    const float* ze = (const float*)d_in[0];
    const float* W  = (const float*)d_in[1];
    const float* mt = (const float*)d_in[2];
    const float* Nt = (const float*)d_in[3];
    float* out = (float*)d_out;
    (void)in_sizes; (void)n_in; (void)out_size;

    cudaFuncSetAttribute(argmin_gemm_kernel,
                         cudaFuncAttributeMaxDynamicSharedMemorySize, SMEM_BYTES);

    zero_kernel<<<2048, 256>>>();
    wsq_kernel<<<(KC * 32) / 256, 256>>>(W);
    conv_ze_kernel<<<(NP * DD) / (256 * 8), 256>>>(ze);
    conv_w_kernel<<<(KC * DD) / (256 * 8), 256>>>(W);
    argmin_gemm_kernel<<<NP / 128, 256, SMEM_BYTES>>>();
    rescore_gather_kernel<<<NP, 256>>>(ze, W, out);
    nt_kernel<<<KC / 256, 256>>>(Nt, out);
    final_kernel<<<(KC * DD) / 256, 256>>>(mt, out);
}

// round 5
// speedup vs baseline: 5.1247x; 1.0073x over previous
#include <cuda_runtime.h>
#include <cuda_fp16.h>
#include <cstdint>

// ---------------------------------------------------------------------------
// QuantizedEmbedding (VQ-VAE codebook + EMA update), GB300 sm_103a
// Round 5: fp16 HMMA with fp16 accumulators (kills register spills),
//          top-4 candidates, exact fp32 rescore.
// ---------------------------------------------------------------------------

#define KC   8192
#define DD   256
#define NP   32768
#define GMA  0.99f
#define OMG  0.01f
#define EPSV 1e-5f

#define OFF_ZQ     0LL
#define OFF_COMMIT 8388608LL
#define OFF_IDX    8388609LL
#define OFF_EW     8421377LL
#define OFF_MT     10518529LL
#define OFF_NT     12615681LL

// ---- device scratch ----
__device__ __align__(256) __half g_Ah[(size_t)NP * DD];   // 16.8 MB fp16 points
__device__ __align__(256) __half g_Bh[(size_t)KC * DD];   //  4.2 MB fp16 codes
__device__ float g_wsq[KC];
__device__ int4  g_cand[NP];
__device__ float g_nt[KC];
__device__ float g_st[KC * DD];
__device__ float g_commit;
__device__ float g_nsum;
__device__ float g_NtNew[KC];

// ===========================================================================
// helpers
// ===========================================================================
__device__ __forceinline__ uint32_t smem_u32(const void* p) {
    uint32_t a;
    asm("{ .reg .u64 t; cvta.to.shared.u64 t, %1; cvt.u32.u64 %0, t; }"
        : "=r"(a) : "l"(p));
    return a;
}
__device__ __forceinline__ void cp16(uint32_t dst, const void* src) {
    asm volatile("cp.async.cg.shared.global [%0], [%1], 16;"
                 :: "r"(dst), "l"(src) : "memory");
}
__device__ __forceinline__ void cp_commit() {
    asm volatile("cp.async.commit_group;" ::: "memory");
}
__device__ __forceinline__ void cp_wait2() {
    asm volatile("cp.async.wait_group 2;" ::: "memory");
}
__device__ __forceinline__ void ldsm4(uint32_t* r, uint32_t addr) {
    asm volatile("ldmatrix.sync.aligned.m8n8.x4.shared.b16 {%0,%1,%2,%3}, [%4];"
                 : "=r"(r[0]), "=r"(r[1]), "=r"(r[2]), "=r"(r[3]) : "r"(addr));
}
// fp16 x fp16 -> fp16 accumulate: C fragment = 2 regs (4 halves)
__device__ __forceinline__ void mma16816h(uint32_t* c, const uint32_t* a,
                                          uint32_t b0, uint32_t b1) {
    asm volatile(
        "mma.sync.aligned.m16n8k16.row.col.f16.f16.f16.f16 "
        "{%0,%1}, {%2,%3,%4,%5}, {%6,%7}, {%0,%1};"
        : "+r"(c[0]), "+r"(c[1])
        : "r"(a[0]), "r"(a[1]), "r"(a[2]), "r"(a[3]), "r"(b0), "r"(b1));
}
__device__ __forceinline__ unsigned fmono(float f) {
    unsigned u = __float_as_uint(f);
    return (u & 0x80000000u) ? ~u : (u | 0x80000000u);
}
__device__ __forceinline__ void ins4(unsigned long long* a, unsigned long long v) {
    if (v < a[3]) {
        if (v < a[2]) {
            a[3] = a[2];
            if (v < a[1]) {
                a[2] = a[1];
                if (v < a[0]) { a[1] = a[0]; a[0] = v; } else a[1] = v;
            } else a[2] = v;
        } else a[3] = v;
    }
}

// ===========================================================================
// small kernels
// ===========================================================================
__global__ void zero_kernel() {
    long long i = (long long)blockIdx.x * blockDim.x + threadIdx.x;
    long long stride = (long long)gridDim.x * blockDim.x;
    for (long long j = i; j < (long long)KC * DD; j += stride) g_st[j] = 0.0f;
    for (long long j = i; j < KC; j += stride) g_nt[j] = 0.0f;
    if (i == 0) { g_commit = 0.0f; g_nsum = 0.0f; }
}

__global__ void wsq_kernel(const float* __restrict__ W) {
    int w = (blockIdx.x * blockDim.x + threadIdx.x) >> 5;
    int lane = threadIdx.x & 31;
    if (w >= KC) return;
    const float4* row = reinterpret_cast<const float4*>(W + (size_t)w * DD);
    float s = 0.0f;
    #pragma unroll
    for (int i = 0; i < 2; i++) {
        float4 v = row[lane + 32 * i];
        s += v.x * v.x + v.y * v.y + v.z * v.z + v.w * v.w;
    }
    #pragma unroll
    for (int o = 16; o; o >>= 1) s += __shfl_down_sync(0xFFFFFFFFu, s, o);
    if (lane == 0) g_wsq[w] = s;
}

__global__ void conv_ze_kernel(const float* __restrict__ src) {
    size_t i = ((size_t)blockIdx.x * 256 + threadIdx.x) * 8;
    float4 v0 = *reinterpret_cast<const float4*>(src + i);
    float4 v1 = *reinterpret_cast<const float4*>(src + i + 4);
    union { uint4 u; __half2 h[4]; } pk;
    pk.h[0] = __floats2half2_rn(v0.x, v0.y);
    pk.h[1] = __floats2half2_rn(v0.z, v0.w);
    pk.h[2] = __floats2half2_rn(v1.x, v1.y);
    pk.h[3] = __floats2half2_rn(v1.z, v1.w);
    *reinterpret_cast<uint4*>(g_Ah + i) = pk.u;
}
__global__ void conv_w_kernel(const float* __restrict__ src) {
    size_t i = ((size_t)blockIdx.x * 256 + threadIdx.x) * 8;
    float4 v0 = *reinterpret_cast<const float4*>(src + i);
    float4 v1 = *reinterpret_cast<const float4*>(src + i + 4);
    union { uint4 u; __half2 h[4]; } pk;
    pk.h[0] = __floats2half2_rn(v0.x, v0.y);
    pk.h[1] = __floats2half2_rn(v0.z, v0.w);
    pk.h[2] = __floats2half2_rn(v1.x, v1.y);
    pk.h[3] = __floats2half2_rn(v1.z, v1.w);
    *reinterpret_cast<uint4*>(g_Bh + i) = pk.u;
}

// ===========================================================================
// HMMA argmin GEMM (fp16 accumulate).
//   CTA: 128 points x 8192 codes. A resident in SMEM (4 k64-chunks, 64 KB).
//   B streamed: 32 N-tiles of 256 codes x 4 k64-chunks, 4-buffer cp.async
//   ring. 8 warps = 2(M) x 4(N); warp tile 64x64; m16n8k16 fp16->fp16.
//   Epilogue: score = wsq - 2*dot, running top-2 per (thread,row); final
//   hierarchical merge -> global top-4 candidates per point.
// ===========================================================================
#define NTILES 32
#define GTOT   128
#define SM_A_BYTES 65536
#define SM_B_BYTES 131072
#define SMEM_BYTES (SM_A_BYTES + SM_B_BYTES)

__device__ __forceinline__ void load_B_chunk(uint32_t dstBase, int nt, int kc,
                                             int tid) {
    const __half* src0 = g_Bh + (size_t)nt * 256 * DD + kc * 64;
    #pragma unroll
    for (int i = 0; i < 8; i++) {
        int v = tid + 256 * i;
        int row = v >> 3, c = v & 7;
        const void* src = src0 + (size_t)row * DD + c * 8;
        uint32_t dst = dstBase + row * 128 + (((c ^ (row & 7))) << 4);
        cp16(dst, src);
    }
}

__global__ void __launch_bounds__(256, 1) argmin_gemm_kernel() {
    extern __shared__ char smem[];
    const uint32_t sb = smem_u32(smem);
    const uint32_t Ab = sb;
    const uint32_t Bb = sb + SM_A_BYTES;

    const int tid  = threadIdx.x;
    const int lane = tid & 31;
    const int wid  = tid >> 5;
    const int R0   = (wid >> 2) * 64;
    const int C0   = (wid & 3) * 64;
    const int n0   = blockIdx.x * 128;

    // ---- prologue: A (resident) + B chunks g=0,1 ----
    #pragma unroll
    for (int i = 0; i < 16; i++) {
        int v = tid + 256 * i;
        int row = v >> 5, gc = v & 31;
        int kc = gc >> 3, c = gc & 7;
        const void* src = g_Ah + (size_t)(n0 + row) * DD + gc * 8;
        uint32_t dst = Ab + kc * 16384 + row * 128 + (((c ^ (row & 7))) << 4);
        cp16(dst, src);
    }
    load_B_chunk(Bb + 0 * 32768, 0, 0, tid);
    cp_commit();
    load_B_chunk(Bb + 1 * 32768, 0, 1, tid);
    cp_commit();

    const int rl = (lane & 7) | (((lane >> 3) & 1) << 3);
    const int kh = (lane >> 4) & 1;

    // fp16 accumulators: [t][j][row-half], each u32 = half2 (2 adjacent cols)
    uint32_t acc[4][8][2];
    #pragma unroll
    for (int t = 0; t < 4; t++)
        #pragma unroll
        for (int j = 0; j < 8; j++) { acc[t][j][0] = 0u; acc[t][j][1] = 0u; }

    const float FINF = __int_as_float(0x7f800000);
    float s1[8], s2[8]; int i1[8], i2[8];
    #pragma unroll
    for (int r = 0; r < 8; r++) { s1[r] = FINF; s2[r] = FINF; i1[r] = 0; i2[r] = 0; }

    for (int g = 0; g < GTOT; ++g) {
        const int kc = g & 3, nt = g >> 2;
        if (g + 2 < GTOT)
            load_B_chunk(Bb + ((g + 2) & 3) * 32768, (g + 2) >> 2, (g + 2) & 3, tid);
        cp_commit();
        cp_wait2();
        __syncthreads();

        const uint32_t Bbuf = Bb + (g & 3) * 32768;
        const uint32_t Achk = Ab + kc * 16384;

        #pragma unroll
        for (int s = 0; s < 4; s++) {
            const int c16 = s * 2 + kh;
            uint32_t a[4][4];
            #pragma unroll
            for (int t = 0; t < 4; t++) {
                int row = R0 + t * 16 + rl;
                uint32_t addr = Achk + row * 128 + (((c16 ^ (row & 7))) << 4);
                ldsm4(a[t], addr);
            }
            uint32_t bf[8][2];
            #pragma unroll
            for (int p = 0; p < 4; p++) {
                int row = C0 + p * 16 + rl;
                uint32_t addr = Bbuf + row * 128 + (((c16 ^ (row & 7))) << 4);
                uint32_t r4[4];
                ldsm4(r4, addr);
                bf[2 * p][0] = r4[0]; bf[2 * p][1] = r4[2];
                bf[2 * p + 1][0] = r4[1]; bf[2 * p + 1][1] = r4[3];
            }
            #pragma unroll
            for (int t = 0; t < 4; t++)
                #pragma unroll
                for (int j = 0; j < 8; j++)
                    mma16816h(acc[t][j], a[t], bf[j][0], bf[j][1]);
        }

        if (kc == 3) {
            // fold tile nt into running top-2 per (thread,row); reset acc
            const int cb0 = nt * 256 + C0 + (lane & 3) * 2;
            #pragma unroll
            for (int j = 0; j < 8; j++) {
                float2 wq = *reinterpret_cast<const float2*>(&g_wsq[cb0 + j * 8]);
                #pragma unroll
                for (int t = 0; t < 4; t++) {
                    #pragma unroll
                    for (int rh = 0; rh < 2; rh++) {
                        const int lr = t * 2 + rh;
                        const float2 dv =
                            __half22float2(*reinterpret_cast<__half2*>(&acc[t][j][rh]));
                        const int col = cb0 + j * 8;
                        const float sc0 = fmaf(-2.0f, dv.x, wq.x);
                        const float sc1 = fmaf(-2.0f, dv.y, wq.y);
                        if (sc0 < s1[lr]) {
                            s2[lr] = s1[lr]; i2[lr] = i1[lr];
                            s1[lr] = sc0;    i1[lr] = col;
                        } else if (sc0 < s2[lr]) {
                            s2[lr] = sc0; i2[lr] = col;
                        }
                        if (sc1 < s1[lr]) {
                            s2[lr] = s1[lr]; i2[lr] = i1[lr];
                            s1[lr] = sc1;    i1[lr] = col + 1;
                        } else if (sc1 < s2[lr]) {
                            s2[lr] = sc1; i2[lr] = col + 1;
                        }
                        acc[t][j][rh] = 0u;
                    }
                }
            }
        }
    }

    // ---- final reduction: quad merge -> smem -> per-row top-4 ----
    unsigned long long* red = reinterpret_cast<unsigned long long*>(smem + SM_A_BYTES);
    const int ni = wid & 3;
    __syncthreads();

    #pragma unroll
    for (int r = 0; r < 8; r++) {
        const int t = r >> 1, h = r & 1;
        const int row = R0 + t * 16 + (lane >> 2) + h * 8;
        unsigned long long arr[4];
        arr[0] = ((unsigned long long)fmono(s1[r]) << 32) | (unsigned)i1[r];
        arr[1] = ((unsigned long long)fmono(s2[r]) << 32) | (unsigned)i2[r];
        arr[2] = ~0ull; arr[3] = ~0ull;
        #pragma unroll
        for (int off = 1; off <= 2; off <<= 1) {
            unsigned long long o0 = __shfl_xor_sync(0xFFFFFFFFu, arr[0], off);
            unsigned long long o1 = __shfl_xor_sync(0xFFFFFFFFu, arr[1], off);
            unsigned long long o2 = __shfl_xor_sync(0xFFFFFFFFu, arr[2], off);
            unsigned long long o3 = __shfl_xor_sync(0xFFFFFFFFu, arr[3], off);
            ins4(arr, o0); ins4(arr, o1); ins4(arr, o2); ins4(arr, o3);
        }
        if ((lane & 3) == 0) {
            #pragma unroll
            for (int k = 0; k < 4; k++) red[(row * 4 + ni) * 4 + k] = arr[k];
        }
    }
    __syncthreads();

    if (tid < 128) {
        unsigned long long a[4] = {~0ull, ~0ull, ~0ull, ~0ull};
        #pragma unroll
        for (int w = 0; w < 4; w++)
            #pragma unroll
            for (int k = 0; k < 4; k++) ins4(a, red[(tid * 4 + w) * 4 + k]);
        g_cand[n0 + tid] = make_int4((int)(a[0] & 0xFFFFFFFFu),
                                     (int)(a[1] & 0xFFFFFFFFu),
                                     (int)(a[2] & 0xFFFFFFFFu),
                                     (int)(a[3] & 0xFFFFFFFFu));
    }
}

// ===========================================================================
// Exact fp32 rescore of top-4 + gather zq + EMA scatter + commit partials
// ===========================================================================
__global__ void rescore_gather_kernel(const float* __restrict__ ze,
                                      const float* __restrict__ W,
                                      float* __restrict__ out) {
    const int n = blockIdx.x;
    const int d = threadIdx.x;
    const int4 c = g_cand[n];
    const float z = ze[(size_t)n * DD + d];
    float w[4], p[4];
    w[0] = W[(size_t)c.x * DD + d];
    w[1] = W[(size_t)c.y * DD + d];
    w[2] = W[(size_t)c.z * DD + d];
    w[3] = W[(size_t)c.w * DD + d];
    #pragma unroll
    for (int j = 0; j < 4; j++) p[j] = z * w[j];
    #pragma unroll
    for (int o = 16; o; o >>= 1)
        #pragma unroll
        for (int j = 0; j < 4; j++)
            p[j] += __shfl_down_sync(0xFFFFFFFFu, p[j], o);
    __shared__ float rp[8][4];
    __shared__ int spick;
    const int lw = d >> 5, ln = d & 31;
    if (ln == 0) {
        #pragma unroll
        for (int j = 0; j < 4; j++) rp[lw][j] = p[j];
    }
    __syncthreads();
    if (d == 0) {
        int ci[4] = {c.x, c.y, c.z, c.w};
        float bs = __int_as_float(0x7f800000);   // +inf
        int bi = 0x7FFFFFFF, bj = 0;
        #pragma unroll
        for (int j = 0; j < 4; j++) {
            float dot = 0.0f;
            #pragma unroll
            for (int i = 0; i < 8; i++) dot += rp[i][j];
            float s = fmaf(-2.0f, dot, g_wsq[ci[j]]);
            if (s < bs || (s == bs && ci[j] < bi)) { bs = s; bi = ci[j]; bj = j; }
        }
        spick = bj;
    }
    __syncthreads();
    const int pick = spick;
    const int cb = (pick == 0) ? c.x : (pick == 1) ? c.y : (pick == 2) ? c.z : c.w;
    const float wv = (pick == 0) ? w[0] : (pick == 1) ? w[1]
                   : (pick == 2) ? w[2] : w[3];
    out[OFF_ZQ + (size_t)n * DD + d] = wv;
    const float diff = wv - z;
    float sq = diff * diff;
    atomicAdd(&g_st[(size_t)cb * DD + d], z);
    #pragma unroll
    for (int o = 16; o; o >>= 1) sq += __shfl_down_sync(0xFFFFFFFFu, sq, o);
    __shared__ float red[8];
    if (ln == 0) red[lw] = sq;
    __syncthreads();
    if (lw == 0) {
        float v = (ln < 8) ? red[ln] : 0.0f;
        #pragma unroll
        for (int o = 4; o; o >>= 1) v += __shfl_down_sync(0xFFFFFFFFu, v, o);
        if (ln == 0) atomicAdd(&g_commit, v);
    }
    if (d == 0) {
        atomicAdd(&g_nt[cb], 1.0f);
        out[OFF_IDX + n] = (float)cb;
    }
}

// ===========================================================================
// Nt / final
// ===========================================================================
__global__ void nt_kernel(const float* __restrict__ Nt, float* __restrict__ out) {
    int k = blockIdx.x * 256 + threadIdx.x;
    float v = GMA * Nt[k] + OMG * g_nt[k];
    g_NtNew[k] = v;
    out[OFF_NT + k] = v;
    float s = v;
    #pragma unroll
    for (int o = 16; o; o >>= 1) s += __shfl_down_sync(0xFFFFFFFFu, s, o);
    __shared__ float red[8];
    int wid = threadIdx.x >> 5, lane = threadIdx.x & 31;
    if (lane == 0) red[wid] = s;
    __syncthreads();
    if (wid == 0) {
        float v2 = (lane < 8) ? red[lane] : 0.0f;
        #pragma unroll
        for (int o = 4; o; o >>= 1) v2 += __shfl_down_sync(0xFFFFFFFFu, v2, o);
        if (lane == 0) atomicAdd(&g_nsum, v2);
    }
}

__global__ void final_kernel(const float* __restrict__ mt, float* __restrict__ out) {
    long long i = (long long)blockIdx.x * 256 + threadIdx.x;
    int k = (int)(i >> 8);
    float mtn = GMA * mt[i] + OMG * g_st[i];
    out[OFF_MT + i] = mtn;
    float n = g_nsum;
    float Nn = (g_NtNew[k] + EPSV) * n / (n + (float)KC * EPSV);
    out[OFF_EW + i] = mtn / Nn;
    if (i == 0) out[OFF_COMMIT] = g_commit / (float)((long long)NP * DD);
}

// ===========================================================================
extern "C" void kernel_launch(void* const* d_in, const int* in_sizes, int n_in,
                              void* d_out, int out_size) {
    const float* ze = (const float*)d_in[0];
    const float* W  = (const float*)d_in[1];
    const float* mt = (const float*)d_in[2];
    const float* Nt = (const float*)d_in[3];
    float* out = (float*)d_out;
    (void)in_sizes; (void)n_in; (void)out_size;

    cudaFuncSetAttribute(argmin_gemm_kernel,
                         cudaFuncAttributeMaxDynamicSharedMemorySize, SMEM_BYTES);

    zero_kernel<<<2048, 256>>>();
    wsq_kernel<<<(KC * 32) / 256, 256>>>(W);
    conv_ze_kernel<<<(NP * DD) / (256 * 8), 256>>>(ze);
    conv_w_kernel<<<(KC * DD) / (256 * 8), 256>>>(W);
    argmin_gemm_kernel<<<NP / 128, 256, SMEM_BYTES>>>();
    rescore_gather_kernel<<<NP, 256>>>(ze, W, out);
    nt_kernel<<<KC / 256, 256>>>(Nt, out);
    final_kernel<<<(KC * DD) / 256, 256>>>(mt, out);
}